// round 4
// baseline (speedup 1.0000x reference)
#include <cuda_runtime.h>
#include <cuda_bf16.h>
#include <math.h>
#include <stdint.h>

// Problem constants
#define NN 32768        // B*K rows
#define DD 256          // feature dim
#define EE 8192         // codebook entries
#define ND (NN*DD)
#define CAP 128         // candidate list capacity per row

// ---------------- scratch (static __device__, no allocation) ----------------
__device__ __align__(16) int8_t g_Aq[NN * DD];
__device__ __align__(16) int8_t g_Bq[EE * DD];
__device__ __align__(16) float g_flatn[NN * DD];   // fp32 normalized inputs
__device__ __align__(16) float g_coden[EE * DD];   // fp32 normalized codebook
__device__ float g_sa[NN];
__device__ float g_sb[EE];
__device__ unsigned int g_sbmax_bits;
__device__ float g_partial[NN / 8];
__device__ float g_scale;
__device__ int   g_idx[NN];
__device__ float g_sim[NN];
__device__ int   g_counts[EE];
__device__ int   g_ccnt[NN];
__device__ int   g_cand[NN * CAP];

// ---------------- PTX helpers ----------------
__device__ __forceinline__ uint32_t smem_u32(const void* p) {
    uint32_t a;
    asm("{ .reg .u64 t; cvta.to.shared.u64 t, %1; cvt.u32.u64 %0, t; }" : "=r"(a) : "l"(p));
    return a;
}
#define CP_ASYNC16(dst, src) \
    asm volatile("cp.async.cg.shared.global [%0], [%1], 16;" :: "r"(dst), "l"(src) : "memory")
#define CP_COMMIT() asm volatile("cp.async.commit_group;" ::: "memory")
#define CP_WAIT1()  asm volatile("cp.async.wait_group 1;" ::: "memory")
#define CP_WAIT0()  asm volatile("cp.async.wait_group 0;" ::: "memory")
#define LDMATRIX_X4(r0, r1, r2, r3, addr) \
    asm volatile("ldmatrix.sync.aligned.m8n8.x4.shared.b16 {%0,%1,%2,%3}, [%4];" \
        : "=r"(r0), "=r"(r1), "=r"(r2), "=r"(r3) : "r"(addr))
#define IMMA16832(c, a, b0, b1) \
    asm volatile("mma.sync.aligned.m16n8k32.row.col.s32.s8.s8.s32 " \
        "{%0,%1,%2,%3}, {%4,%5,%6,%7}, {%8,%9}, {%0,%1,%2,%3};" \
        : "+r"((c)[0]), "+r"((c)[1]), "+r"((c)[2]), "+r"((c)[3]) \
        : "r"((a)[0]), "r"((a)[1]), "r"((a)[2]), "r"((a)[3]), "r"(b0), "r"(b1))

// ---------------- zero counters ----------------
__global__ void zero_kernel() {
    int i = blockIdx.x * 256 + threadIdx.x;
    if (i < EE) g_counts[i] = 0;
    if (i < NN) g_ccnt[i] = 0;
    if (i == 0) g_sbmax_bits = 0u;
}

__device__ __forceinline__ uint32_t pack4(int a, int b, int c, int d) {
    return (uint32_t)(a & 255) | ((uint32_t)(b & 255) << 8) |
           ((uint32_t)(c & 255) << 16) | ((uint32_t)(d & 255) << 24);
}

// ---------------- normalize inputs -> fp32 + int8 + scales + norm sums ------
__global__ void normalize_inputs_kernel(const float* __restrict__ in) {
    int warp = threadIdx.x >> 5, lane = threadIdx.x & 31;
    int row = blockIdx.x * 8 + warp;
    __shared__ float sh[8];
    const float4* r = (const float4*)in + (size_t)row * 64;
    float4 v0 = r[lane], v1 = r[lane + 32];
    float s = v0.x*v0.x + v0.y*v0.y + v0.z*v0.z + v0.w*v0.w
            + v1.x*v1.x + v1.y*v1.y + v1.z*v1.z + v1.w*v1.w;
#pragma unroll
    for (int off = 16; off; off >>= 1) s += __shfl_down_sync(0xffffffffu, s, off);
    s = __shfl_sync(0xffffffffu, s, 0);
    float nrm = sqrtf(s);
    float inv = 1.0f / fmaxf(nrm, 1e-12f);
    float4 n0 = make_float4(v0.x*inv, v0.y*inv, v0.z*inv, v0.w*inv);
    float4 n1 = make_float4(v1.x*inv, v1.y*inv, v1.z*inv, v1.w*inv);
    ((float4*)g_flatn)[(size_t)row * 64 + lane]      = n0;
    ((float4*)g_flatn)[(size_t)row * 64 + 32 + lane] = n1;

    float am = fmaxf(fmaxf(fmaxf(fabsf(n0.x), fabsf(n0.y)), fmaxf(fabsf(n0.z), fabsf(n0.w))),
                     fmaxf(fmaxf(fabsf(n1.x), fabsf(n1.y)), fmaxf(fabsf(n1.z), fabsf(n1.w))));
#pragma unroll
    for (int off = 16; off; off >>= 1) am = fmaxf(am, __shfl_down_sync(0xffffffffu, am, off));
    am = __shfl_sync(0xffffffffu, am, 0);
    float qs = 127.0f / fmaxf(am, 1e-20f);
    uint32_t p0 = pack4(__float2int_rn(n0.x*qs), __float2int_rn(n0.y*qs),
                        __float2int_rn(n0.z*qs), __float2int_rn(n0.w*qs));
    uint32_t p1 = pack4(__float2int_rn(n1.x*qs), __float2int_rn(n1.y*qs),
                        __float2int_rn(n1.z*qs), __float2int_rn(n1.w*qs));
    ((uint32_t*)g_Aq)[(size_t)row * 64 + lane]      = p0;
    ((uint32_t*)g_Aq)[(size_t)row * 64 + 32 + lane] = p1;
    if (lane == 0) g_sa[row] = am / 127.0f;

    if (lane == 0) sh[warp] = nrm;
    __syncthreads();
    if (threadIdx.x == 0) {
        float t = 0.f;
#pragma unroll
        for (int w = 0; w < 8; w++) t += sh[w];
        g_partial[blockIdx.x] = t;
    }
}

// ---------------- normalize codebook -> fp32 + int8 + scales ----------------
__global__ void normalize_codebook_kernel(const float* __restrict__ in) {
    int warp = threadIdx.x >> 5, lane = threadIdx.x & 31;
    int row = blockIdx.x * 8 + warp;
    const float4* r = (const float4*)in + (size_t)row * 64;
    float4 v0 = r[lane], v1 = r[lane + 32];
    float s = v0.x*v0.x + v0.y*v0.y + v0.z*v0.z + v0.w*v0.w
            + v1.x*v1.x + v1.y*v1.y + v1.z*v1.z + v1.w*v1.w;
#pragma unroll
    for (int off = 16; off; off >>= 1) s += __shfl_down_sync(0xffffffffu, s, off);
    s = __shfl_sync(0xffffffffu, s, 0);
    float inv = 1.0f / fmaxf(sqrtf(s), 1e-12f);
    float4 n0 = make_float4(v0.x*inv, v0.y*inv, v0.z*inv, v0.w*inv);
    float4 n1 = make_float4(v1.x*inv, v1.y*inv, v1.z*inv, v1.w*inv);
    ((float4*)g_coden)[(size_t)row * 64 + lane]      = n0;
    ((float4*)g_coden)[(size_t)row * 64 + 32 + lane] = n1;

    float am = fmaxf(fmaxf(fmaxf(fabsf(n0.x), fabsf(n0.y)), fmaxf(fabsf(n0.z), fabsf(n0.w))),
                     fmaxf(fmaxf(fabsf(n1.x), fabsf(n1.y)), fmaxf(fabsf(n1.z), fabsf(n1.w))));
#pragma unroll
    for (int off = 16; off; off >>= 1) am = fmaxf(am, __shfl_down_sync(0xffffffffu, am, off));
    am = __shfl_sync(0xffffffffu, am, 0);
    float qs = 127.0f / fmaxf(am, 1e-20f);
    uint32_t p0 = pack4(__float2int_rn(n0.x*qs), __float2int_rn(n0.y*qs),
                        __float2int_rn(n0.z*qs), __float2int_rn(n0.w*qs));
    uint32_t p1 = pack4(__float2int_rn(n1.x*qs), __float2int_rn(n1.y*qs),
                        __float2int_rn(n1.z*qs), __float2int_rn(n1.w*qs));
    ((uint32_t*)g_Bq)[(size_t)row * 64 + lane]      = p0;
    ((uint32_t*)g_Bq)[(size_t)row * 64 + 32 + lane] = p1;
    if (lane == 0) {
        float sb = am / 127.0f;
        g_sb[row] = sb;
        atomicMax(&g_sbmax_bits, __float_as_uint(sb));
    }
}

// ---------------- deterministic mean-scale reduction ------------------------
__global__ void reduce_scale_kernel() {
    __shared__ float sh[256];
    float s = 0.f;
    for (int i = threadIdx.x; i < NN / 8; i += 256) s += g_partial[i];
    sh[threadIdx.x] = s; __syncthreads();
    for (int off = 128; off; off >>= 1) {
        if (threadIdx.x < off) sh[threadIdx.x] += sh[threadIdx.x + off];
        __syncthreads();
    }
    if (threadIdx.x == 0) g_scale = sh[0] / (float)NN;
}

// ---------------- int8 IMMA GEMM + running max + candidate capture ----------
// 128x128 CTA tile, 8 warps 4m x 2n (warp tile 32x64). A resident (128x256
// int8 = 32KB, swizzled). B streamed in 128x128-int8 k-chunks (16KB),
// double-buffered cp.async; sb (code scales) staged per tile.
#define OFF_B   32768
#define OFF_SB  (32768 + 2 * 16384)
#define SMEM_GEMM (OFF_SB + 2 * 512)

__device__ __forceinline__ uint32_t a_off(uint32_t r, uint32_t ch) {
    return r * 256u + (((ch & 0x8u) | ((ch ^ r) & 7u)) << 4);
}
__device__ __forceinline__ uint32_t b_off(uint32_t c, uint32_t ch) {
    return c * 128u + (((ch ^ c) & 7u) << 4);
}

__global__ void __launch_bounds__(256, 2) qq_gemm_kernel() {
    extern __shared__ __align__(1024) char smem[];
    const uint32_t sb = smem_u32(smem);
    const int tid = threadIdx.x;
    const int wid = tid >> 5;
    const int lane = tid & 31;
    const int warp_m = wid & 3;
    const int warp_n = wid >> 2;
    const int row0 = blockIdx.x * 128;

    // ---- A resident load (group 0): 2048 x 16B ----
    {
        const uint4* Ag = (const uint4*)g_Aq;
#pragma unroll
        for (int l = 0; l < 8; l++) {
            int id = tid + l * 256;          // 0..2047
            uint32_t r = id >> 4, ch = id & 15;
            uint32_t dst = sb + a_off(r, ch);
            const uint4* src = Ag + (size_t)(row0 + r) * 16 + ch;
            CP_ASYNC16(dst, src);
        }
    }
    CP_COMMIT();

    const uint4* Bg = (const uint4*)g_Bq;
    // issue stage i: tile t = i>>1, k-chunk kc = i&1, buffer i&1; sb on kc==0
#define ISSUE_STAGE(i) do { \
        int _t = (i) >> 1, _kc = (i) & 1; \
        uint32_t _bb = sb + OFF_B + ((i) & 1) * 16384; \
        _Pragma("unroll") \
        for (int _l = 0; _l < 4; _l++) { \
            int _id = tid + _l * 256; \
            uint32_t _c = _id >> 3, _ch = _id & 7; \
            uint32_t _dst = _bb + b_off(_c, _ch); \
            const uint4* _src = Bg + (size_t)(_t * 128 + _c) * 16 + _kc * 8 + _ch; \
            CP_ASYNC16(_dst, _src); \
        } \
        if (_kc == 0 && tid < 32) { \
            uint32_t _dst = sb + OFF_SB + (_t & 1) * 512 + tid * 16; \
            const float4* _src = (const float4*)g_sb + _t * 32 + tid; \
            CP_ASYNC16(_dst, _src); \
        } \
    } while (0)

    ISSUE_STAGE(0);
    CP_COMMIT();

    // per-thread row scales and margins
    float sa4[4], marg4[4];
    {
        float sbmax = __uint_as_float(g_sbmax_bits);
#pragma unroll
        for (int s = 0; s < 4; s++) {
            int rl = warp_m * 32 + (s >> 1) * 16 + (lane >> 2) + (s & 1) * 8;
            float sa = g_sa[row0 + rl];
            sa4[s] = sa;
            marg4[s] = 2.0f * (8.0f * (sa + sbmax) + 192.0f * sa * sbmax) + 1e-4f;
        }
    }

    int c[2][8][4];
    float bestv[4] = {-1e30f, -1e30f, -1e30f, -1e30f};

    for (int i = 0; i < 128; i++) {
        const int kc = i & 1;
        const int t = i >> 1;
        if (i + 1 < 128) {
            ISSUE_STAGE(i + 1);
            CP_COMMIT();
            CP_WAIT1();
        } else {
            CP_WAIT0();
        }
        __syncthreads();

        if (kc == 0) {
#pragma unroll
            for (int mi = 0; mi < 2; mi++)
#pragma unroll
                for (int ni = 0; ni < 8; ni++)
#pragma unroll
                    for (int r2 = 0; r2 < 4; r2++) c[mi][ni][r2] = 0;
        }

        const uint32_t bb = sb + OFF_B + (i & 1) * 16384;
#pragma unroll
        for (int ks = 0; ks < 4; ks++) {
            uint32_t a[2][4];
#pragma unroll
            for (int mi = 0; mi < 2; mi++) {
                uint32_t r = warp_m * 32 + mi * 16 + (lane & 15);
                uint32_t ch = kc * 8 + ks * 2 + (lane >> 4);
                uint32_t addr = sb + a_off(r, ch);
                LDMATRIX_X4(a[mi][0], a[mi][1], a[mi][2], a[mi][3], addr);
            }
            uint32_t b[4][4];
#pragma unroll
            for (int np = 0; np < 4; np++) {
                uint32_t code = warp_n * 64 + np * 16 + (lane & 7) + ((lane & 16) ? 8 : 0);
                uint32_t ch = ks * 2 + ((lane >> 3) & 1);
                uint32_t addr = bb + b_off(code, ch);
                LDMATRIX_X4(b[np][0], b[np][1], b[np][2], b[np][3], addr);
            }
#pragma unroll
            for (int mi = 0; mi < 2; mi++)
#pragma unroll
                for (int ni = 0; ni < 8; ni++)
                    IMMA16832(c[mi][ni], a[mi], b[ni >> 1][(ni & 1) * 2], b[ni >> 1][(ni & 1) * 2 + 1]);
        }

        // ---- per-tile epilogue after last k-chunk ----
        if (kc == 1) {
            const uint32_t sboff = sb + OFF_SB + (t & 1) * 512;
            float sbv[8][2];
#pragma unroll
            for (int ni = 0; ni < 8; ni++) {
                float2 p = *(const float2*)(smem + (sboff - sb) + (warp_n * 64 + ni * 8 + (lane & 3) * 2) * 4);
                sbv[ni][0] = p.x; sbv[ni][1] = p.y;
            }
#pragma unroll
            for (int s = 0; s < 4; s++) {
                const int mi = s >> 1, hf = s & 1;
                float v[8][2];
                float m = -1e30f;
#pragma unroll
                for (int ni = 0; ni < 8; ni++) {
#pragma unroll
                    for (int r2 = 0; r2 < 2; r2++) {
                        float x = sa4[s] * sbv[ni][r2] * (float)c[mi][ni][hf * 2 + r2];
                        v[ni][r2] = x;
                        m = fmaxf(m, x);
                    }
                }
                m = fmaxf(m, __shfl_xor_sync(0xffffffffu, m, 1));
                m = fmaxf(m, __shfl_xor_sync(0xffffffffu, m, 2));
                bestv[s] = fmaxf(bestv[s], m);
                const float thr = bestv[s] - marg4[s];
                const int row = row0 + warp_m * 32 + mi * 16 + (lane >> 2) + hf * 8;
#pragma unroll
                for (int ni = 0; ni < 8; ni++) {
#pragma unroll
                    for (int r2 = 0; r2 < 2; r2++) {
                        if (v[ni][r2] >= thr) {
                            int col = t * 128 + warp_n * 64 + ni * 8 + (lane & 3) * 2 + r2;
                            int slot = atomicAdd(&g_ccnt[row], 1);
                            if (slot < CAP) g_cand[row * CAP + slot] = col;
                        }
                    }
                }
            }
        }
        __syncthreads();
    }
}

// ---------------- exact fp32 refine over candidates -------------------------
__global__ void refine_kernel() {
    const int wid = threadIdx.x >> 5, lane = threadIdx.x & 31;
    const int row = blockIdx.x * 8 + wid;
    const float4* F = (const float4*)g_flatn + (size_t)row * 64 + lane * 2;
    const float4 f0 = F[0], f1 = F[1];
    int cnt = g_ccnt[row];
    float bv = -1e30f;
    int bi = 0x7fffffff;

    if (cnt <= CAP) {
        for (int j = 0; j < cnt; j++) {
            int cidx = g_cand[row * CAP + j];
            const float4* G = (const float4*)g_coden + (size_t)cidx * 64 + lane * 2;
            float4 g0 = G[0], g1 = G[1];
            float s = f0.x*g0.x + f0.y*g0.y + f0.z*g0.z + f0.w*g0.w
                    + f1.x*g1.x + f1.y*g1.y + f1.z*g1.z + f1.w*g1.w;
#pragma unroll
            for (int off = 16; off; off >>= 1) s += __shfl_xor_sync(0xffffffffu, s, off);
            if (s > bv || (s == bv && cidx < bi)) { bv = s; bi = cidx; }
        }
    } else {
        for (int cidx = 0; cidx < EE; cidx++) {
            const float4* G = (const float4*)g_coden + (size_t)cidx * 64 + lane * 2;
            float4 g0 = G[0], g1 = G[1];
            float s = f0.x*g0.x + f0.y*g0.y + f0.z*g0.z + f0.w*g0.w
                    + f1.x*g1.x + f1.y*g1.y + f1.z*g1.z + f1.w*g1.w;
#pragma unroll
            for (int off = 16; off; off >>= 1) s += __shfl_xor_sync(0xffffffffu, s, off);
            if (s > bv || (s == bv && cidx < bi)) { bv = s; bi = cidx; }
        }
    }
    if (lane == 0) {
        g_idx[row] = bi;
        g_sim[row] = bv;
    }
}

// ---------------- bincount ----------------
__global__ void bincount_kernel() {
    int i = blockIdx.x * 256 + threadIdx.x;
    atomicAdd(&g_counts[g_idx[i]], 1);
}

// ---------------- quantized output ----------------
__global__ void write_quant_kernel(float* __restrict__ out) {
    int i = blockIdx.x * 256 + threadIdx.x;
    float s = g_scale;
    int n = i >> 6, d4 = i & 63;
    float4 v = ((const float4*)g_coden)[(size_t)g_idx[n] * 64 + d4];
    v.x *= s; v.y *= s; v.z *= s; v.w *= s;
    ((float4*)out)[i] = v;
}

// ---------------- loss + perplexity ----------------
__global__ void finalize_kernel(float* __restrict__ out) {
    __shared__ float sh[256];
    int tid = threadIdx.x;
    float s = 0.f;
    for (int i = tid; i < NN; i += 256) s += g_sim[i];
    sh[tid] = s; __syncthreads();
    for (int off = 128; off; off >>= 1) {
        if (tid < off) sh[tid] += sh[tid + off];
        __syncthreads();
    }
    float sumS = sh[0];
    __syncthreads();
    float h = 0.f;
    for (int i = tid; i < EE; i += 256) {
        float p = (float)g_counts[i] / (float)NN;
        h -= p * logf(p + 1e-10f);
    }
    sh[tid] = h; __syncthreads();
    for (int off = 128; off; off >>= 1) {
        if (tid < off) sh[tid] += sh[tid + off];
        __syncthreads();
    }
    if (tid == 0) {
        float loss = 1.25f * (2.0f * (float)NN - 2.0f * sumS) / (float)ND;
        out[ND]     = loss;
        out[ND + 1] = expf(sh[0]);
    }
}

// ---------------- launch ----------------
extern "C" void kernel_launch(void* const* d_in, const int* in_sizes, int n_in,
                              void* d_out, int out_size) {
    const float* inputs   = (const float*)d_in[0];
    const float* codebook = (const float*)d_in[1];
    float* out = (float*)d_out;

    cudaFuncSetAttribute(qq_gemm_kernel, cudaFuncAttributeMaxDynamicSharedMemorySize, SMEM_GEMM);

    zero_kernel<<<NN / 256, 256>>>();
    normalize_inputs_kernel<<<NN / 8, 256>>>(inputs);
    normalize_codebook_kernel<<<EE / 8, 256>>>(codebook);
    reduce_scale_kernel<<<1, 256>>>();
    qq_gemm_kernel<<<NN / 128, 256, SMEM_GEMM>>>();
    refine_kernel<<<NN / 8, 256>>>();
    bincount_kernel<<<NN / 256, 256>>>();
    write_quant_kernel<<<ND / 4 / 256, 256>>>(out);
    finalize_kernel<<<1, 256>>>(out);
}

// round 5
// speedup vs baseline: 17.5884x; 17.5884x over previous
#include <cuda_runtime.h>
#include <cuda_bf16.h>
#include <math.h>
#include <stdint.h>

// Problem constants
#define NN 32768        // B*K rows
#define DD 256          // feature dim
#define EE 8192         // codebook entries
#define ND (NN*DD)
#define CAP 128         // candidate list capacity per row
#define MARGIN 0.012f   // bf16 rounding slack (2 * 2^-8 + headroom)
#define NUNITS 2048     // 256 row-tiles x 8 code-chunks (1024 codes each)

// ---------------- scratch (static __device__, no allocation) ----------------
__device__ __align__(16) __nv_bfloat16 g_Abf[NN * DD];
__device__ __align__(16) __nv_bfloat16 g_Bbf[EE * DD];
__device__ __align__(16) float g_flatn[NN * DD];   // fp32 normalized inputs
__device__ __align__(16) float g_coden[EE * DD];   // fp32 normalized codebook
__device__ float g_partial[NN / 8];
__device__ float g_scale;
__device__ int   g_idx[NN];
__device__ float g_sim[NN];
__device__ int   g_counts[EE];
__device__ int   g_ccnt[NN];
__device__ int   g_cand[NN * CAP];

// ---------------- PTX helpers ----------------
__device__ __forceinline__ uint32_t smem_u32(const void* p) {
    uint32_t a;
    asm("{ .reg .u64 t; cvta.to.shared.u64 t, %1; cvt.u32.u64 %0, t; }" : "=r"(a) : "l"(p));
    return a;
}
#define CP_ASYNC16(dst, src) \
    asm volatile("cp.async.cg.shared.global [%0], [%1], 16;" :: "r"(dst), "l"(src) : "memory")
#define CP_COMMIT() asm volatile("cp.async.commit_group;" ::: "memory")
#define CP_WAIT1()  asm volatile("cp.async.wait_group 1;" ::: "memory")
#define CP_WAIT0()  asm volatile("cp.async.wait_group 0;" ::: "memory")
#define LDMATRIX_X4(r0, r1, r2, r3, addr) \
    asm volatile("ldmatrix.sync.aligned.m8n8.x4.shared.b16 {%0,%1,%2,%3}, [%4];" \
        : "=r"(r0), "=r"(r1), "=r"(r2), "=r"(r3) : "r"(addr))
#define MMA16816(c, a, b0, b1) \
    asm volatile("mma.sync.aligned.m16n8k16.row.col.f32.bf16.bf16.f32 " \
        "{%0,%1,%2,%3}, {%4,%5,%6,%7}, {%8,%9}, {%0,%1,%2,%3};" \
        : "+f"((c)[0]), "+f"((c)[1]), "+f"((c)[2]), "+f"((c)[3]) \
        : "r"((a)[0]), "r"((a)[1]), "r"((a)[2]), "r"((a)[3]), "r"(b0), "r"(b1))

// ---------------- normalize inputs -> fp32 + bf16 + norm sums + zero ccnt ---
__global__ void normalize_inputs_kernel(const float* __restrict__ in) {
    // fused zero of candidate counters (first 128 blocks cover NN ints)
    if (blockIdx.x < 128) g_ccnt[blockIdx.x * 256 + threadIdx.x] = 0;

    int warp = threadIdx.x >> 5, lane = threadIdx.x & 31;
    int row = blockIdx.x * 8 + warp;
    __shared__ float sh[8];
    const float4* r = (const float4*)in + (size_t)row * 64;
    float4 v0 = r[lane], v1 = r[lane + 32];
    float s = v0.x*v0.x + v0.y*v0.y + v0.z*v0.z + v0.w*v0.w
            + v1.x*v1.x + v1.y*v1.y + v1.z*v1.z + v1.w*v1.w;
#pragma unroll
    for (int off = 16; off; off >>= 1) s += __shfl_down_sync(0xffffffffu, s, off);
    s = __shfl_sync(0xffffffffu, s, 0);
    float nrm = sqrtf(s);
    float inv = 1.0f / fmaxf(nrm, 1e-12f);
    float4 n0 = make_float4(v0.x*inv, v0.y*inv, v0.z*inv, v0.w*inv);
    float4 n1 = make_float4(v1.x*inv, v1.y*inv, v1.z*inv, v1.w*inv);
    ((float4*)g_flatn)[(size_t)row * 64 + lane]      = n0;
    ((float4*)g_flatn)[(size_t)row * 64 + 32 + lane] = n1;
    __nv_bfloat162 b0 = __floats2bfloat162_rn(n0.x, n0.y);
    __nv_bfloat162 b1 = __floats2bfloat162_rn(n0.z, n0.w);
    __nv_bfloat162 b2 = __floats2bfloat162_rn(n1.x, n1.y);
    __nv_bfloat162 b3 = __floats2bfloat162_rn(n1.z, n1.w);
    uint2 h0 = make_uint2(*(uint32_t*)&b0, *(uint32_t*)&b1);
    uint2 h1 = make_uint2(*(uint32_t*)&b2, *(uint32_t*)&b3);
    ((uint2*)g_Abf)[(size_t)row * 64 + lane]      = h0;
    ((uint2*)g_Abf)[(size_t)row * 64 + 32 + lane] = h1;

    if (lane == 0) sh[warp] = nrm;
    __syncthreads();
    if (threadIdx.x == 0) {
        float t = 0.f;
#pragma unroll
        for (int w = 0; w < 8; w++) t += sh[w];
        g_partial[blockIdx.x] = t;
    }
}

// ---------------- normalize codebook -> fp32 + bf16 + zero counts -----------
__global__ void normalize_codebook_kernel(const float* __restrict__ in) {
    if (blockIdx.x < 32) g_counts[blockIdx.x * 256 + threadIdx.x] = 0;

    int warp = threadIdx.x >> 5, lane = threadIdx.x & 31;
    int row = blockIdx.x * 8 + warp;
    const float4* r = (const float4*)in + (size_t)row * 64;
    float4 v0 = r[lane], v1 = r[lane + 32];
    float s = v0.x*v0.x + v0.y*v0.y + v0.z*v0.z + v0.w*v0.w
            + v1.x*v1.x + v1.y*v1.y + v1.z*v1.z + v1.w*v1.w;
#pragma unroll
    for (int off = 16; off; off >>= 1) s += __shfl_down_sync(0xffffffffu, s, off);
    s = __shfl_sync(0xffffffffu, s, 0);
    float inv = 1.0f / fmaxf(sqrtf(s), 1e-12f);
    float4 n0 = make_float4(v0.x*inv, v0.y*inv, v0.z*inv, v0.w*inv);
    float4 n1 = make_float4(v1.x*inv, v1.y*inv, v1.z*inv, v1.w*inv);
    ((float4*)g_coden)[(size_t)row * 64 + lane]      = n0;
    ((float4*)g_coden)[(size_t)row * 64 + 32 + lane] = n1;
    __nv_bfloat162 b0 = __floats2bfloat162_rn(n0.x, n0.y);
    __nv_bfloat162 b1 = __floats2bfloat162_rn(n0.z, n0.w);
    __nv_bfloat162 b2 = __floats2bfloat162_rn(n1.x, n1.y);
    __nv_bfloat162 b3 = __floats2bfloat162_rn(n1.z, n1.w);
    uint2 h0 = make_uint2(*(uint32_t*)&b0, *(uint32_t*)&b1);
    uint2 h1 = make_uint2(*(uint32_t*)&b2, *(uint32_t*)&b3);
    ((uint2*)g_Bbf)[(size_t)row * 64 + lane]      = h0;
    ((uint2*)g_Bbf)[(size_t)row * 64 + 32 + lane] = h1;
}

// ---------------- bf16 mma.sync persistent GEMM + candidate capture ---------
// Work unit = 128 rows x 1024 codes. 2048 units round-robined over the
// persistent grid (deterministic, no atomic tickets). Per unit: A tile
// (128x256 bf16, 64KB swizzled) loaded, B streamed as 8 code-tiles x 4
// k-chunks (16KB stages, double-buffered cp.async). Unit-local running max +
// margin append keeps the exact-argmax superset guarantee.
#define SMEM_GEMM (65536 + 2 * 16384)

__device__ __forceinline__ uint32_t a_off(uint32_t r, uint32_t ch) {
    return r * 512u + (((ch & 0x18u) | ((ch ^ r) & 7u)) << 4);
}
__device__ __forceinline__ uint32_t b_off(uint32_t c, uint32_t ch) {
    return c * 128u + (((ch ^ c) & 7u) << 4);
}

__global__ void __launch_bounds__(256, 2) hh_gemm_kernel() {
    extern __shared__ __align__(1024) char smem[];
    const uint32_t sb = smem_u32(smem);
    const int tid = threadIdx.x;
    const int wid = tid >> 5;
    const int lane = tid & 31;
    const int warp_m = wid & 3;
    const int warp_n = wid >> 2;
    const uint4* Ag = (const uint4*)g_Abf;
    const uint4* Bg = (const uint4*)g_Bbf;

    for (int u = blockIdx.x; u < NUNITS; u += gridDim.x) {
        const int rt = u >> 3;
        const int cc = u & 7;
        const int row0 = rt * 128;
        const int col0 = cc * 1024;

        // ---- A tile load (own cp group) ----
#pragma unroll
        for (int l = 0; l < 16; l++) {
            int id = tid + l * 256;          // 0..4095
            uint32_t r = id >> 5, ch = id & 31;
            uint32_t dst = sb + a_off(r, ch);
            CP_ASYNC16(dst, Ag + (size_t)(row0 + r) * 32 + ch);
        }
        CP_COMMIT();

        // issue stage i (i in 0..31): code tile t = i>>2, k-chunk kc = i&3
#define ISSUE_STAGE(i) do { \
            int _t = (i) >> 2, _kc = (i) & 3; \
            uint32_t _bb = sb + 65536 + ((i) & 1) * 16384; \
            _Pragma("unroll") \
            for (int _l = 0; _l < 4; _l++) { \
                int _id = tid + _l * 256; \
                uint32_t _c = _id >> 3, _ch = _id & 7; \
                uint32_t _dst = _bb + b_off(_c, _ch); \
                CP_ASYNC16(_dst, Bg + (size_t)(col0 + _t * 128 + _c) * 32 + _kc * 8 + _ch); \
            } \
        } while (0)

        ISSUE_STAGE(0);
        CP_COMMIT();

        float c[2][8][4];
        float bestv[4] = {-1e30f, -1e30f, -1e30f, -1e30f};

        for (int i = 0; i < 32; i++) {
            const int kc = i & 3;
            const int t = i >> 2;
            if (i + 1 < 32) {
                ISSUE_STAGE(i + 1);
                CP_COMMIT();
                CP_WAIT1();
            } else {
                CP_WAIT0();
            }
            __syncthreads();

            if (kc == 0) {
#pragma unroll
                for (int mi = 0; mi < 2; mi++)
#pragma unroll
                    for (int ni = 0; ni < 8; ni++)
#pragma unroll
                        for (int r2 = 0; r2 < 4; r2++) c[mi][ni][r2] = 0.f;
            }

            const uint32_t bb = sb + 65536 + (i & 1) * 16384;
#pragma unroll
            for (int ks = 0; ks < 4; ks++) {
                uint32_t a[2][4];
#pragma unroll
                for (int mi = 0; mi < 2; mi++) {
                    uint32_t r = warp_m * 32 + mi * 16 + (lane & 15);
                    uint32_t ch = kc * 8 + ks * 2 + (lane >> 4);
                    uint32_t addr = sb + a_off(r, ch);
                    LDMATRIX_X4(a[mi][0], a[mi][1], a[mi][2], a[mi][3], addr);
                }
                uint32_t b[4][4];
#pragma unroll
                for (int np = 0; np < 4; np++) {
                    uint32_t code = warp_n * 64 + np * 16 + (lane & 7) + ((lane & 16) ? 8 : 0);
                    uint32_t ch = ks * 2 + ((lane >> 3) & 1);
                    uint32_t addr = bb + b_off(code, ch);
                    LDMATRIX_X4(b[np][0], b[np][1], b[np][2], b[np][3], addr);
                }
#pragma unroll
                for (int mi = 0; mi < 2; mi++)
#pragma unroll
                    for (int ni = 0; ni < 8; ni++)
                        MMA16816(c[mi][ni], a[mi], b[ni >> 1][(ni & 1) * 2], b[ni >> 1][(ni & 1) * 2 + 1]);
            }

            // ---- per-code-tile epilogue ----
            if (kc == 3) {
#pragma unroll
                for (int s = 0; s < 4; s++) {
                    const int mi = s >> 1, hf = s & 1;
                    float m = c[mi][0][hf * 2];
#pragma unroll
                    for (int ni = 0; ni < 8; ni++) {
                        m = fmaxf(m, c[mi][ni][hf * 2]);
                        m = fmaxf(m, c[mi][ni][hf * 2 + 1]);
                    }
                    m = fmaxf(m, __shfl_xor_sync(0xffffffffu, m, 1));
                    m = fmaxf(m, __shfl_xor_sync(0xffffffffu, m, 2));
                    bestv[s] = fmaxf(bestv[s], m);
                    const float thr = bestv[s] - MARGIN;
                    const int row = row0 + warp_m * 32 + mi * 16 + (lane >> 2) + hf * 8;
#pragma unroll
                    for (int ni = 0; ni < 8; ni++) {
#pragma unroll
                        for (int r2 = 0; r2 < 2; r2++) {
                            float v = c[mi][ni][hf * 2 + r2];
                            if (v >= thr) {
                                int col = col0 + t * 128 + warp_n * 64 + ni * 8 + (lane & 3) * 2 + r2;
                                int slot = atomicAdd(&g_ccnt[row], 1);
                                if (slot < CAP) g_cand[row * CAP + slot] = col;
                            }
                        }
                    }
                }
            }
            __syncthreads();
        }
#undef ISSUE_STAGE
    }
}

// ---------------- exact fp32 refine + fused bincount + fused scale ----------
__global__ void refine_kernel() {
    // fused mean-scale reduction in block 0
    if (blockIdx.x == 0) {
        __shared__ float sh[256];
        float s = 0.f;
        for (int i = threadIdx.x; i < NN / 8; i += 256) s += g_partial[i];
        sh[threadIdx.x] = s; __syncthreads();
        for (int off = 128; off; off >>= 1) {
            if (threadIdx.x < off) sh[threadIdx.x] += sh[threadIdx.x + off];
            __syncthreads();
        }
        if (threadIdx.x == 0) g_scale = sh[0] / (float)NN;
    }

    const int wid = threadIdx.x >> 5, lane = threadIdx.x & 31;
    const int row = blockIdx.x * 8 + wid;
    const float4* F = (const float4*)g_flatn + (size_t)row * 64 + lane * 2;
    const float4 f0 = F[0], f1 = F[1];
    int cnt = g_ccnt[row];
    float bv = -1e30f;
    int bi = 0x7fffffff;

    if (cnt <= CAP) {
        for (int j = 0; j < cnt; j++) {
            int cidx = g_cand[row * CAP + j];
            const float4* G = (const float4*)g_coden + (size_t)cidx * 64 + lane * 2;
            float4 g0 = G[0], g1 = G[1];
            float s = f0.x*g0.x + f0.y*g0.y + f0.z*g0.z + f0.w*g0.w
                    + f1.x*g1.x + f1.y*g1.y + f1.z*g1.z + f1.w*g1.w;
#pragma unroll
            for (int off = 16; off; off >>= 1) s += __shfl_xor_sync(0xffffffffu, s, off);
            if (s > bv || (s == bv && cidx < bi)) { bv = s; bi = cidx; }
        }
    } else {
        // overflow fallback: exact scan over all codes
        for (int cidx = 0; cidx < EE; cidx++) {
            const float4* G = (const float4*)g_coden + (size_t)cidx * 64 + lane * 2;
            float4 g0 = G[0], g1 = G[1];
            float s = f0.x*g0.x + f0.y*g0.y + f0.z*g0.z + f0.w*g0.w
                    + f1.x*g1.x + f1.y*g1.y + f1.z*g1.z + f1.w*g1.w;
#pragma unroll
            for (int off = 16; off; off >>= 1) s += __shfl_xor_sync(0xffffffffu, s, off);
            if (s > bv || (s == bv && cidx < bi)) { bv = s; bi = cidx; }
        }
    }
    if (lane == 0) {
        g_idx[row] = bi;
        g_sim[row] = bv;
        atomicAdd(&g_counts[bi], 1);   // fused bincount (integer: deterministic)
    }
}

// ---------------- quantized output ----------------
__global__ void write_quant_kernel(float* __restrict__ out) {
    int i = blockIdx.x * 256 + threadIdx.x;
    float s = g_scale;
    int n = i >> 6, d4 = i & 63;
    float4 v = ((const float4*)g_coden)[(size_t)g_idx[n] * 64 + d4];
    v.x *= s; v.y *= s; v.z *= s; v.w *= s;
    ((float4*)out)[i] = v;
}

// ---------------- loss + perplexity ----------------
__global__ void finalize_kernel(float* __restrict__ out) {
    __shared__ float sh[256];
    int tid = threadIdx.x;
    float s = 0.f;
    for (int i = tid; i < NN; i += 256) s += g_sim[i];
    sh[tid] = s; __syncthreads();
    for (int off = 128; off; off >>= 1) {
        if (tid < off) sh[tid] += sh[tid + off];
        __syncthreads();
    }
    float sumS = sh[0];
    __syncthreads();
    float h = 0.f;
    for (int i = tid; i < EE; i += 256) {
        float p = (float)g_counts[i] / (float)NN;
        h -= p * logf(p + 1e-10f);
    }
    sh[tid] = h; __syncthreads();
    for (int off = 128; off; off >>= 1) {
        if (tid < off) sh[tid] += sh[tid + off];
        __syncthreads();
    }
    if (tid == 0) {
        float loss = 1.25f * (2.0f * (float)NN - 2.0f * sumS) / (float)ND;
        out[ND]     = loss;
        out[ND + 1] = expf(sh[0]);
    }
}

// ---------------- launch ----------------
extern "C" void kernel_launch(void* const* d_in, const int* in_sizes, int n_in,
                              void* d_out, int out_size) {
    const float* inputs   = (const float*)d_in[0];
    const float* codebook = (const float*)d_in[1];
    float* out = (float*)d_out;

    cudaFuncSetAttribute(hh_gemm_kernel, cudaFuncAttributeMaxDynamicSharedMemorySize, SMEM_GEMM);

    normalize_inputs_kernel<<<NN / 8, 256>>>(inputs);
    normalize_codebook_kernel<<<EE / 8, 256>>>(codebook);
    hh_gemm_kernel<<<296, 256, SMEM_GEMM>>>();
    refine_kernel<<<NN / 8, 256>>>();
    write_quant_kernel<<<ND / 4 / 256, 256>>>(out);
    finalize_kernel<<<1, 256>>>(out);
}

// round 6
// speedup vs baseline: 29.3260x; 1.6674x over previous
#include <cuda_runtime.h>
#include <cuda_bf16.h>
#include <math.h>
#include <stdint.h>

// Problem constants
#define NN 32768        // B*K rows
#define DD 256          // feature dim
#define EE 8192         // codebook entries
#define ND (NN*DD)
#define CAP 128         // candidate list capacity per row
#define MARGIN 0.012f   // bf16 rounding slack (2 * 2^-8 + headroom)
#define NTILES 16384    // 256 row-tiles x 64 code-tiles (128 codes each)
#define NG 296          // persistent grid (2 CTAs per SM on 148 SMs)

// ---------------- scratch (static __device__, no allocation) ----------------
__device__ __align__(16) __nv_bfloat16 g_Abf[NN * DD];
__device__ __align__(16) __nv_bfloat16 g_Bbf[EE * DD];
__device__ __align__(16) float g_flatn[NN * DD];   // fp32 normalized inputs
__device__ __align__(16) float g_coden[EE * DD];   // fp32 normalized codebook
__device__ float g_partial[NN / 8];
__device__ float g_scale;
__device__ int   g_idx[NN];
__device__ float g_sim[NN];
__device__ int   g_counts[EE];
__device__ int   g_ccnt[NN];
__device__ unsigned int g_rowmax[NN];              // monotone shared row max (keyed)
__device__ int   g_cand[NN * CAP];

// ---------------- PTX helpers ----------------
__device__ __forceinline__ uint32_t smem_u32(const void* p) {
    uint32_t a;
    asm("{ .reg .u64 t; cvta.to.shared.u64 t, %1; cvt.u32.u64 %0, t; }" : "=r"(a) : "l"(p));
    return a;
}
#define CP_ASYNC16(dst, src) \
    asm volatile("cp.async.cg.shared.global [%0], [%1], 16;" :: "r"(dst), "l"(src) : "memory")
#define CP_COMMIT() asm volatile("cp.async.commit_group;" ::: "memory")
#define CP_WAIT1()  asm volatile("cp.async.wait_group 1;" ::: "memory")
#define CP_WAIT0()  asm volatile("cp.async.wait_group 0;" ::: "memory")
#define LDMATRIX_X4(r0, r1, r2, r3, addr) \
    asm volatile("ldmatrix.sync.aligned.m8n8.x4.shared.b16 {%0,%1,%2,%3}, [%4];" \
        : "=r"(r0), "=r"(r1), "=r"(r2), "=r"(r3) : "r"(addr))
#define MMA16816(c, a, b0, b1) \
    asm volatile("mma.sync.aligned.m16n8k16.row.col.f32.bf16.bf16.f32 " \
        "{%0,%1,%2,%3}, {%4,%5,%6,%7}, {%8,%9}, {%0,%1,%2,%3};" \
        : "+f"((c)[0]), "+f"((c)[1]), "+f"((c)[2]), "+f"((c)[3]) \
        : "r"((a)[0]), "r"((a)[1]), "r"((a)[2]), "r"((a)[3]), "r"(b0), "r"(b1))

// order-preserving float<->uint key (for atomicMax on possibly-negative floats)
__device__ __forceinline__ uint32_t fkey(float f) {
    uint32_t u = __float_as_uint(f);
    return (u & 0x80000000u) ? ~u : (u | 0x80000000u);
}
__device__ __forceinline__ float funkey(uint32_t k) {
    uint32_t u = (k & 0x80000000u) ? (k & 0x7fffffffu) : ~k;
    return __uint_as_float(u);
}

// ---------------- normalize inputs (+ fused inits) --------------------------
__global__ void normalize_inputs_kernel(const float* __restrict__ in) {
    // fused zero of per-row candidate counters and shared row max
    if (blockIdx.x < 128) {
        int z = blockIdx.x * 256 + threadIdx.x;
        g_ccnt[z] = 0;
        g_rowmax[z] = 0u;        // key(-inf)
    }

    int warp = threadIdx.x >> 5, lane = threadIdx.x & 31;
    int row = blockIdx.x * 8 + warp;
    __shared__ float sh[8];
    const float4* r = (const float4*)in + (size_t)row * 64;
    float4 v0 = r[lane], v1 = r[lane + 32];
    float s = v0.x*v0.x + v0.y*v0.y + v0.z*v0.z + v0.w*v0.w
            + v1.x*v1.x + v1.y*v1.y + v1.z*v1.z + v1.w*v1.w;
#pragma unroll
    for (int off = 16; off; off >>= 1) s += __shfl_down_sync(0xffffffffu, s, off);
    s = __shfl_sync(0xffffffffu, s, 0);
    float nrm = sqrtf(s);
    float inv = 1.0f / fmaxf(nrm, 1e-12f);
    float4 n0 = make_float4(v0.x*inv, v0.y*inv, v0.z*inv, v0.w*inv);
    float4 n1 = make_float4(v1.x*inv, v1.y*inv, v1.z*inv, v1.w*inv);
    ((float4*)g_flatn)[(size_t)row * 64 + lane]      = n0;
    ((float4*)g_flatn)[(size_t)row * 64 + 32 + lane] = n1;
    __nv_bfloat162 b0 = __floats2bfloat162_rn(n0.x, n0.y);
    __nv_bfloat162 b1 = __floats2bfloat162_rn(n0.z, n0.w);
    __nv_bfloat162 b2 = __floats2bfloat162_rn(n1.x, n1.y);
    __nv_bfloat162 b3 = __floats2bfloat162_rn(n1.z, n1.w);
    uint2 h0 = make_uint2(*(uint32_t*)&b0, *(uint32_t*)&b1);
    uint2 h1 = make_uint2(*(uint32_t*)&b2, *(uint32_t*)&b3);
    ((uint2*)g_Abf)[(size_t)row * 64 + lane]      = h0;
    ((uint2*)g_Abf)[(size_t)row * 64 + 32 + lane] = h1;

    if (lane == 0) sh[warp] = nrm;
    __syncthreads();
    if (threadIdx.x == 0) {
        float t = 0.f;
#pragma unroll
        for (int w = 0; w < 8; w++) t += sh[w];
        g_partial[blockIdx.x] = t;
    }
}

// ---------------- normalize codebook (+ fused counts zero) ------------------
__global__ void normalize_codebook_kernel(const float* __restrict__ in) {
    if (blockIdx.x < 32) g_counts[blockIdx.x * 256 + threadIdx.x] = 0;

    int warp = threadIdx.x >> 5, lane = threadIdx.x & 31;
    int row = blockIdx.x * 8 + warp;
    const float4* r = (const float4*)in + (size_t)row * 64;
    float4 v0 = r[lane], v1 = r[lane + 32];
    float s = v0.x*v0.x + v0.y*v0.y + v0.z*v0.z + v0.w*v0.w
            + v1.x*v1.x + v1.y*v1.y + v1.z*v1.z + v1.w*v1.w;
#pragma unroll
    for (int off = 16; off; off >>= 1) s += __shfl_down_sync(0xffffffffu, s, off);
    s = __shfl_sync(0xffffffffu, s, 0);
    float inv = 1.0f / fmaxf(sqrtf(s), 1e-12f);
    float4 n0 = make_float4(v0.x*inv, v0.y*inv, v0.z*inv, v0.w*inv);
    float4 n1 = make_float4(v1.x*inv, v1.y*inv, v1.z*inv, v1.w*inv);
    ((float4*)g_coden)[(size_t)row * 64 + lane]      = n0;
    ((float4*)g_coden)[(size_t)row * 64 + 32 + lane] = n1;
    __nv_bfloat162 b0 = __floats2bfloat162_rn(n0.x, n0.y);
    __nv_bfloat162 b1 = __floats2bfloat162_rn(n0.z, n0.w);
    __nv_bfloat162 b2 = __floats2bfloat162_rn(n1.x, n1.y);
    __nv_bfloat162 b3 = __floats2bfloat162_rn(n1.z, n1.w);
    uint2 h0 = make_uint2(*(uint32_t*)&b0, *(uint32_t*)&b1);
    uint2 h1 = make_uint2(*(uint32_t*)&b2, *(uint32_t*)&b3);
    ((uint2*)g_Bbf)[(size_t)row * 64 + lane]      = h0;
    ((uint2*)g_Bbf)[(size_t)row * 64 + 32 + lane] = h1;
}

// ---------------- balanced persistent bf16 GEMM + candidate capture ---------
// Work = 16384 tiles (row-tile rt in 0..255, code-tile tc in 0..63, tile =
// 128 rows x 128 codes x full K). CTA b owns the contiguous range
// [b*16384/296, (b+1)*16384/296) -> 55-56 tiles, <=2 A reloads, 1.2% max
// imbalance. Shared monotone per-row max (g_rowmax, atomicMax publish, __ldcg
// refresh consumed one tile later) keeps capture thresholds near-global so
// candidate counts stay small. Margin superset guarantee: threshold <= final
// approx max, and approx(c*) >= approx_max - 2*bf16err > threshold.
#define SMEM_GEMM (65536 + 2 * 16384)

__device__ __forceinline__ uint32_t a_off(uint32_t r, uint32_t ch) {
    return r * 512u + (((ch & 0x18u) | ((ch ^ r) & 7u)) << 4);
}
__device__ __forceinline__ uint32_t b_off(uint32_t c, uint32_t ch) {
    return c * 128u + (((ch ^ c) & 7u) << 4);
}

__global__ void __launch_bounds__(256, 2) hh_gemm_kernel() {
    extern __shared__ __align__(1024) char smem[];
    const uint32_t sb = smem_u32(smem);
    const int tid = threadIdx.x;
    const int wid = tid >> 5;
    const int lane = tid & 31;
    const int warp_m = wid & 3;
    const int warp_n = wid >> 2;
    const uint4* Ag = (const uint4*)g_Abf;
    const uint4* Bg = (const uint4*)g_Bbf;

    const int u0 = (int)(((long long)blockIdx.x * NTILES) / NG);
    const int u1 = (int)(((long long)(blockIdx.x + 1) * NTILES) / NG);

    int i = u0;
    while (i < u1) {
        const int rt = i >> 6;
        const int row0 = rt * 128;
        const int segend = min(u1, (rt + 1) << 6);
        const int nj = (segend - i) * 4;

        // ---- A tile load (own cp group) ----
#pragma unroll
        for (int l = 0; l < 16; l++) {
            int id = tid + l * 256;          // 0..4095
            uint32_t r = id >> 5, ch = id & 31;
            CP_ASYNC16(sb + a_off(r, ch), Ag + (size_t)(row0 + r) * 32 + ch);
        }
        CP_COMMIT();

        // ---- per-segment row state ----
        float bestv[4], cached[4];
        int rows4[4];
#pragma unroll
        for (int s = 0; s < 4; s++) {
            rows4[s] = row0 + warp_m * 32 + (s >> 1) * 16 + (lane >> 2) + (s & 1) * 8;
            bestv[s] = -1e30f;
            cached[s] = funkey(__ldcg(&g_rowmax[rows4[s]]));
        }

        // issue stage j: tile = i + (j>>2), k-chunk kc = j&3, buffer j&1
#define ISSUE_STAGE(j) do { \
            int _tl = i + ((j) >> 2), _kc = (j) & 3; \
            int _cb = (_tl & 63) * 128; \
            uint32_t _bb = sb + 65536 + ((j) & 1) * 16384; \
            _Pragma("unroll") \
            for (int _l = 0; _l < 4; _l++) { \
                int _id = tid + _l * 256; \
                uint32_t _c = _id >> 3, _ch = _id & 7; \
                CP_ASYNC16(_bb + b_off(_c, _ch), Bg + (size_t)(_cb + _c) * 32 + _kc * 8 + _ch); \
            } \
        } while (0)

        ISSUE_STAGE(0);
        CP_COMMIT();

        float c[2][8][4];

        for (int j = 0; j < nj; j++) {
            const int kc = j & 3;
            if (j + 1 < nj) {
                ISSUE_STAGE(j + 1);
                CP_COMMIT();
                CP_WAIT1();
            } else {
                CP_WAIT0();
            }
            __syncthreads();

            if (kc == 0) {
#pragma unroll
                for (int mi = 0; mi < 2; mi++)
#pragma unroll
                    for (int ni = 0; ni < 8; ni++)
#pragma unroll
                        for (int r2 = 0; r2 < 4; r2++) c[mi][ni][r2] = 0.f;
            }

            const uint32_t bb = sb + 65536 + (j & 1) * 16384;
#pragma unroll
            for (int ks = 0; ks < 4; ks++) {
                uint32_t a[2][4];
#pragma unroll
                for (int mi = 0; mi < 2; mi++) {
                    uint32_t r = warp_m * 32 + mi * 16 + (lane & 15);
                    uint32_t ch = kc * 8 + ks * 2 + (lane >> 4);
                    uint32_t addr = sb + a_off(r, ch);
                    LDMATRIX_X4(a[mi][0], a[mi][1], a[mi][2], a[mi][3], addr);
                }
                uint32_t b[4][4];
#pragma unroll
                for (int np = 0; np < 4; np++) {
                    uint32_t code = warp_n * 64 + np * 16 + (lane & 7) + ((lane & 16) ? 8 : 0);
                    uint32_t ch = ks * 2 + ((lane >> 3) & 1);
                    uint32_t addr = bb + b_off(code, ch);
                    LDMATRIX_X4(b[np][0], b[np][1], b[np][2], b[np][3], addr);
                }
#pragma unroll
                for (int mi = 0; mi < 2; mi++)
#pragma unroll
                    for (int ni = 0; ni < 8; ni++)
                        MMA16816(c[mi][ni], a[mi], b[ni >> 1][(ni & 1) * 2], b[ni >> 1][(ni & 1) * 2 + 1]);
            }

            // ---- per-tile epilogue ----
            if (kc == 3) {
                const int colbase = ((i + (j >> 2)) & 63) * 128;
#pragma unroll
                for (int s = 0; s < 4; s++) {
                    const int mi = s >> 1, hf = s & 1;
                    float m = c[mi][0][hf * 2];
#pragma unroll
                    for (int ni = 0; ni < 8; ni++) {
                        m = fmaxf(m, c[mi][ni][hf * 2]);
                        m = fmaxf(m, c[mi][ni][hf * 2 + 1]);
                    }
                    m = fmaxf(m, __shfl_xor_sync(0xffffffffu, m, 1));
                    m = fmaxf(m, __shfl_xor_sync(0xffffffffu, m, 2));
                    bestv[s] = fmaxf(fmaxf(bestv[s], m), cached[s]);
                    const float thr = bestv[s] - MARGIN;
                    const int row = rows4[s];
#pragma unroll
                    for (int ni = 0; ni < 8; ni++) {
#pragma unroll
                        for (int r2 = 0; r2 < 2; r2++) {
                            float v = c[mi][ni][hf * 2 + r2];
                            if (v >= thr) {
                                int col = colbase + warp_n * 64 + ni * 8 + (lane & 3) * 2 + r2;
                                int slot = atomicAdd(&g_ccnt[row], 1);
                                if (slot < CAP) g_cand[row * CAP + slot] = col;
                            }
                        }
                    }
                    // publish + refresh (consumed next tile; latency hidden)
                    if ((lane & 3) == 0) atomicMax(&g_rowmax[row], fkey(bestv[s]));
                    cached[s] = funkey(__ldcg(&g_rowmax[row]));
                }
            }
            __syncthreads();
        }
#undef ISSUE_STAGE
        i = segend;
    }
}

// ---------------- exact fp32 refine + fused bincount + fused scale ----------
__global__ void refine_kernel() {
    // fused mean-scale reduction in block 0
    if (blockIdx.x == 0) {
        __shared__ float sh[256];
        float s = 0.f;
        for (int i = threadIdx.x; i < NN / 8; i += 256) s += g_partial[i];
        sh[threadIdx.x] = s; __syncthreads();
        for (int off = 128; off; off >>= 1) {
            if (threadIdx.x < off) sh[threadIdx.x] += sh[threadIdx.x + off];
            __syncthreads();
        }
        if (threadIdx.x == 0) g_scale = sh[0] / (float)NN;
    }

    const int wid = threadIdx.x >> 5, lane = threadIdx.x & 31;
    const int row = blockIdx.x * 8 + wid;
    const float4* F = (const float4*)g_flatn + (size_t)row * 64 + lane * 2;
    const float4 f0 = F[0], f1 = F[1];
    int cnt = g_ccnt[row];
    float bv = -1e30f;
    int bi = 0x7fffffff;

    if (cnt <= CAP) {
        for (int j = 0; j < cnt; j++) {
            int cidx = g_cand[row * CAP + j];
            const float4* G = (const float4*)g_coden + (size_t)cidx * 64 + lane * 2;
            float4 g0 = G[0], g1 = G[1];
            float s = f0.x*g0.x + f0.y*g0.y + f0.z*g0.z + f0.w*g0.w
                    + f1.x*g1.x + f1.y*g1.y + f1.z*g1.z + f1.w*g1.w;
#pragma unroll
            for (int off = 16; off; off >>= 1) s += __shfl_xor_sync(0xffffffffu, s, off);
            if (s > bv || (s == bv && cidx < bi)) { bv = s; bi = cidx; }
        }
    } else {
        // overflow fallback: exact scan over all codes
        for (int cidx = 0; cidx < EE; cidx++) {
            const float4* G = (const float4*)g_coden + (size_t)cidx * 64 + lane * 2;
            float4 g0 = G[0], g1 = G[1];
            float s = f0.x*g0.x + f0.y*g0.y + f0.z*g0.z + f0.w*g0.w
                    + f1.x*g1.x + f1.y*g1.y + f1.z*g1.z + f1.w*g1.w;
#pragma unroll
            for (int off = 16; off; off >>= 1) s += __shfl_xor_sync(0xffffffffu, s, off);
            if (s > bv || (s == bv && cidx < bi)) { bv = s; bi = cidx; }
        }
    }
    if (lane == 0) {
        g_idx[row] = bi;
        g_sim[row] = bv;
        atomicAdd(&g_counts[bi], 1);   // fused bincount (integer: deterministic)
    }
}

// ---------------- quantized output ----------------
__global__ void write_quant_kernel(float* __restrict__ out) {
    int i = blockIdx.x * 256 + threadIdx.x;
    float s = g_scale;
    int n = i >> 6, d4 = i & 63;
    float4 v = ((const float4*)g_coden)[(size_t)g_idx[n] * 64 + d4];
    v.x *= s; v.y *= s; v.z *= s; v.w *= s;
    ((float4*)out)[i] = v;
}

// ---------------- loss + perplexity ----------------
__global__ void finalize_kernel(float* __restrict__ out) {
    __shared__ float sh[256];
    int tid = threadIdx.x;
    float s = 0.f;
    for (int i = tid; i < NN; i += 256) s += g_sim[i];
    sh[tid] = s; __syncthreads();
    for (int off = 128; off; off >>= 1) {
        if (tid < off) sh[tid] += sh[tid + off];
        __syncthreads();
    }
    float sumS = sh[0];
    __syncthreads();
    float h = 0.f;
    for (int i = tid; i < EE; i += 256) {
        float p = (float)g_counts[i] / (float)NN;
        h -= p * logf(p + 1e-10f);
    }
    sh[tid] = h; __syncthreads();
    for (int off = 128; off; off >>= 1) {
        if (tid < off) sh[tid] += sh[tid + off];
        __syncthreads();
    }
    if (tid == 0) {
        float loss = 1.25f * (2.0f * (float)NN - 2.0f * sumS) / (float)ND;
        out[ND]     = loss;
        out[ND + 1] = expf(sh[0]);
    }
}

// ---------------- launch ----------------
extern "C" void kernel_launch(void* const* d_in, const int* in_sizes, int n_in,
                              void* d_out, int out_size) {
    const float* inputs   = (const float*)d_in[0];
    const float* codebook = (const float*)d_in[1];
    float* out = (float*)d_out;

    cudaFuncSetAttribute(hh_gemm_kernel, cudaFuncAttributeMaxDynamicSharedMemorySize, SMEM_GEMM);

    normalize_inputs_kernel<<<NN / 8, 256>>>(inputs);
    normalize_codebook_kernel<<<EE / 8, 256>>>(codebook);
    hh_gemm_kernel<<<NG, 256, SMEM_GEMM>>>();
    refine_kernel<<<NN / 8, 256>>>();
    write_quant_kernel<<<ND / 4 / 256, 256>>>(out);
    finalize_kernel<<<1, 256>>>(out);
}

// round 7
// speedup vs baseline: 31.4657x; 1.0730x over previous
#include <cuda_runtime.h>
#include <cuda_fp16.h>
#include <math.h>
#include <stdint.h>

// Problem constants
#define NN 32768        // B*K rows
#define DD 256          // feature dim
#define EE 8192         // codebook entries
#define ND (NN*DD)
#define CAP 128         // candidate list capacity per row
#define MARGIN 0.003f   // fp16 rounding slack (2 * 2^-10 + headroom)
#define NTILES 16384    // 256 row-tiles x 64 code-tiles (128 codes each)
#define NG 296          // persistent grid (2 CTAs per SM on 148 SMs)

// ---------------- scratch (static __device__, no allocation) ----------------
__device__ __align__(16) __half g_Ah[NN * DD];
__device__ __align__(16) __half g_Bh[EE * DD];
__device__ __align__(16) float g_flatn[NN * DD];   // fp32 normalized inputs
__device__ __align__(16) float g_coden[EE * DD];   // fp32 normalized codebook
__device__ float g_partial[NN / 8];
__device__ float g_scale;
__device__ int   g_idx[NN];
__device__ float g_sim[NN];
__device__ int   g_counts[EE];
__device__ int   g_ccnt[NN];
__device__ unsigned int g_rowmax[NN];              // monotone shared row max (keyed)
__device__ int   g_cand[NN * CAP];

// ---------------- PTX helpers ----------------
__device__ __forceinline__ uint32_t smem_u32(const void* p) {
    uint32_t a;
    asm("{ .reg .u64 t; cvta.to.shared.u64 t, %1; cvt.u32.u64 %0, t; }" : "=r"(a) : "l"(p));
    return a;
}
#define CP_ASYNC16(dst, src) \
    asm volatile("cp.async.cg.shared.global [%0], [%1], 16;" :: "r"(dst), "l"(src) : "memory")
#define CP_COMMIT() asm volatile("cp.async.commit_group;" ::: "memory")
#define CP_WAIT1()  asm volatile("cp.async.wait_group 1;" ::: "memory")
#define CP_WAIT0()  asm volatile("cp.async.wait_group 0;" ::: "memory")
#define LDMATRIX_X4(r0, r1, r2, r3, addr) \
    asm volatile("ldmatrix.sync.aligned.m8n8.x4.shared.b16 {%0,%1,%2,%3}, [%4];" \
        : "=r"(r0), "=r"(r1), "=r"(r2), "=r"(r3) : "r"(addr))
#define MMA16816(c, a, b0, b1) \
    asm volatile("mma.sync.aligned.m16n8k16.row.col.f32.f16.f16.f32 " \
        "{%0,%1,%2,%3}, {%4,%5,%6,%7}, {%8,%9}, {%0,%1,%2,%3};" \
        : "+f"((c)[0]), "+f"((c)[1]), "+f"((c)[2]), "+f"((c)[3]) \
        : "r"((a)[0]), "r"((a)[1]), "r"((a)[2]), "r"((a)[3]), "r"(b0), "r"(b1))

// order-preserving float<->uint key (for atomicMax on possibly-negative floats)
__device__ __forceinline__ uint32_t fkey(float f) {
    uint32_t u = __float_as_uint(f);
    return (u & 0x80000000u) ? ~u : (u | 0x80000000u);
}
__device__ __forceinline__ float funkey(uint32_t k) {
    uint32_t u = (k & 0x80000000u) ? (k & 0x7fffffffu) : ~k;
    return __uint_as_float(u);
}

// ---------------- normalize inputs (+ fused inits) --------------------------
__global__ void normalize_inputs_kernel(const float* __restrict__ in) {
    // fused zero of per-row candidate counters and shared row max
    if (blockIdx.x < 128) {
        int z = blockIdx.x * 256 + threadIdx.x;
        g_ccnt[z] = 0;
        g_rowmax[z] = 0u;        // key(-inf)
    }

    int warp = threadIdx.x >> 5, lane = threadIdx.x & 31;
    int row = blockIdx.x * 8 + warp;
    __shared__ float sh[8];
    const float4* r = (const float4*)in + (size_t)row * 64;
    float4 v0 = r[lane], v1 = r[lane + 32];
    float s = v0.x*v0.x + v0.y*v0.y + v0.z*v0.z + v0.w*v0.w
            + v1.x*v1.x + v1.y*v1.y + v1.z*v1.z + v1.w*v1.w;
#pragma unroll
    for (int off = 16; off; off >>= 1) s += __shfl_down_sync(0xffffffffu, s, off);
    s = __shfl_sync(0xffffffffu, s, 0);
    float nrm = sqrtf(s);
    float inv = 1.0f / fmaxf(nrm, 1e-12f);
    float4 n0 = make_float4(v0.x*inv, v0.y*inv, v0.z*inv, v0.w*inv);
    float4 n1 = make_float4(v1.x*inv, v1.y*inv, v1.z*inv, v1.w*inv);
    ((float4*)g_flatn)[(size_t)row * 64 + lane]      = n0;
    ((float4*)g_flatn)[(size_t)row * 64 + 32 + lane] = n1;
    __half2 h0a = __floats2half2_rn(n0.x, n0.y);
    __half2 h0b = __floats2half2_rn(n0.z, n0.w);
    __half2 h1a = __floats2half2_rn(n1.x, n1.y);
    __half2 h1b = __floats2half2_rn(n1.z, n1.w);
    uint2 h0 = make_uint2(*(uint32_t*)&h0a, *(uint32_t*)&h0b);
    uint2 h1 = make_uint2(*(uint32_t*)&h1a, *(uint32_t*)&h1b);
    ((uint2*)g_Ah)[(size_t)row * 64 + lane]      = h0;
    ((uint2*)g_Ah)[(size_t)row * 64 + 32 + lane] = h1;

    if (lane == 0) sh[warp] = nrm;
    __syncthreads();
    if (threadIdx.x == 0) {
        float t = 0.f;
#pragma unroll
        for (int w = 0; w < 8; w++) t += sh[w];
        g_partial[blockIdx.x] = t;
    }
}

// ---------------- normalize codebook (+ fused counts zero + scale) ----------
__global__ void normalize_codebook_kernel(const float* __restrict__ in) {
    if (blockIdx.x < 32) g_counts[blockIdx.x * 256 + threadIdx.x] = 0;

    // fused deterministic mean-scale reduction (g_partial is complete:
    // previous kernel on the same stream)
    if (blockIdx.x == EE / 8 - 1) {
        __shared__ float shp[256];
        float s = 0.f;
        for (int i = threadIdx.x; i < NN / 8; i += 256) s += g_partial[i];
        shp[threadIdx.x] = s; __syncthreads();
        for (int off = 128; off; off >>= 1) {
            if (threadIdx.x < off) shp[threadIdx.x] += shp[threadIdx.x + off];
            __syncthreads();
        }
        if (threadIdx.x == 0) g_scale = shp[0] / (float)NN;
        __syncthreads();
    }

    int warp = threadIdx.x >> 5, lane = threadIdx.x & 31;
    int row = blockIdx.x * 8 + warp;
    const float4* r = (const float4*)in + (size_t)row * 64;
    float4 v0 = r[lane], v1 = r[lane + 32];
    float s = v0.x*v0.x + v0.y*v0.y + v0.z*v0.z + v0.w*v0.w
            + v1.x*v1.x + v1.y*v1.y + v1.z*v1.z + v1.w*v1.w;
#pragma unroll
    for (int off = 16; off; off >>= 1) s += __shfl_down_sync(0xffffffffu, s, off);
    s = __shfl_sync(0xffffffffu, s, 0);
    float inv = 1.0f / fmaxf(sqrtf(s), 1e-12f);
    float4 n0 = make_float4(v0.x*inv, v0.y*inv, v0.z*inv, v0.w*inv);
    float4 n1 = make_float4(v1.x*inv, v1.y*inv, v1.z*inv, v1.w*inv);
    ((float4*)g_coden)[(size_t)row * 64 + lane]      = n0;
    ((float4*)g_coden)[(size_t)row * 64 + 32 + lane] = n1;
    __half2 h0a = __floats2half2_rn(n0.x, n0.y);
    __half2 h0b = __floats2half2_rn(n0.z, n0.w);
    __half2 h1a = __floats2half2_rn(n1.x, n1.y);
    __half2 h1b = __floats2half2_rn(n1.z, n1.w);
    uint2 h0 = make_uint2(*(uint32_t*)&h0a, *(uint32_t*)&h0b);
    uint2 h1 = make_uint2(*(uint32_t*)&h1a, *(uint32_t*)&h1b);
    ((uint2*)g_Bh)[(size_t)row * 64 + lane]      = h0;
    ((uint2*)g_Bh)[(size_t)row * 64 + 32 + lane] = h1;
}

// ---------------- balanced persistent fp16 GEMM + candidate capture ---------
// Work = 16384 tiles (128 rows x 128 codes x full K). CTA b owns a contiguous
// range (55-56 tiles, <=2 A reloads, 1.2% imbalance). Shared monotone per-row
// max keeps capture thresholds near-global. fp16 margin: per-dot error
// <= 2^-10, two dots compared -> 0.00195 < MARGIN=0.003.
#define SMEM_GEMM (65536 + 2 * 16384)

__device__ __forceinline__ uint32_t a_off(uint32_t r, uint32_t ch) {
    return r * 512u + (((ch & 0x18u) | ((ch ^ r) & 7u)) << 4);
}
__device__ __forceinline__ uint32_t b_off(uint32_t c, uint32_t ch) {
    return c * 128u + (((ch ^ c) & 7u) << 4);
}

__global__ void __launch_bounds__(256, 2) hh_gemm_kernel() {
    extern __shared__ __align__(1024) char smem[];
    const uint32_t sb = smem_u32(smem);
    const int tid = threadIdx.x;
    const int wid = tid >> 5;
    const int lane = tid & 31;
    const int warp_m = wid & 3;
    const int warp_n = wid >> 2;
    const uint4* Ag = (const uint4*)g_Ah;
    const uint4* Bg = (const uint4*)g_Bh;

    const int u0 = (int)(((long long)blockIdx.x * NTILES) / NG);
    const int u1 = (int)(((long long)(blockIdx.x + 1) * NTILES) / NG);

    int i = u0;
    while (i < u1) {
        const int rt = i >> 6;
        const int row0 = rt * 128;
        const int segend = min(u1, (rt + 1) << 6);
        const int nj = (segend - i) * 4;

        // ---- A tile load (own cp group) ----
#pragma unroll
        for (int l = 0; l < 16; l++) {
            int id = tid + l * 256;          // 0..4095
            uint32_t r = id >> 5, ch = id & 31;
            CP_ASYNC16(sb + a_off(r, ch), Ag + (size_t)(row0 + r) * 32 + ch);
        }
        CP_COMMIT();

        // ---- per-segment row state ----
        float bestv[4], cached[4];
        int rows4[4];
#pragma unroll
        for (int s = 0; s < 4; s++) {
            rows4[s] = row0 + warp_m * 32 + (s >> 1) * 16 + (lane >> 2) + (s & 1) * 8;
            bestv[s] = -1e30f;
            cached[s] = funkey(__ldcg(&g_rowmax[rows4[s]]));
        }

        // issue stage j: tile = i + (j>>2), k-chunk kc = j&3, buffer j&1
#define ISSUE_STAGE(j) do { \
            int _tl = i + ((j) >> 2), _kc = (j) & 3; \
            int _cb = (_tl & 63) * 128; \
            uint32_t _bb = sb + 65536 + ((j) & 1) * 16384; \
            _Pragma("unroll") \
            for (int _l = 0; _l < 4; _l++) { \
                int _id = tid + _l * 256; \
                uint32_t _c = _id >> 3, _ch = _id & 7; \
                CP_ASYNC16(_bb + b_off(_c, _ch), Bg + (size_t)(_cb + _c) * 32 + _kc * 8 + _ch); \
            } \
        } while (0)

        ISSUE_STAGE(0);
        CP_COMMIT();

        float c[2][8][4];

        for (int j = 0; j < nj; j++) {
            const int kc = j & 3;
            if (j + 1 < nj) {
                ISSUE_STAGE(j + 1);
                CP_COMMIT();
                CP_WAIT1();
            } else {
                CP_WAIT0();
            }
            __syncthreads();

            if (kc == 0) {
#pragma unroll
                for (int mi = 0; mi < 2; mi++)
#pragma unroll
                    for (int ni = 0; ni < 8; ni++)
#pragma unroll
                        for (int r2 = 0; r2 < 4; r2++) c[mi][ni][r2] = 0.f;
            }

            const uint32_t bb = sb + 65536 + (j & 1) * 16384;
#pragma unroll
            for (int ks = 0; ks < 4; ks++) {
                uint32_t a[2][4];
#pragma unroll
                for (int mi = 0; mi < 2; mi++) {
                    uint32_t r = warp_m * 32 + mi * 16 + (lane & 15);
                    uint32_t ch = kc * 8 + ks * 2 + (lane >> 4);
                    uint32_t addr = sb + a_off(r, ch);
                    LDMATRIX_X4(a[mi][0], a[mi][1], a[mi][2], a[mi][3], addr);
                }
                uint32_t b[4][4];
#pragma unroll
                for (int np = 0; np < 4; np++) {
                    uint32_t code = warp_n * 64 + np * 16 + (lane & 7) + ((lane & 16) ? 8 : 0);
                    uint32_t ch = ks * 2 + ((lane >> 3) & 1);
                    uint32_t addr = bb + b_off(code, ch);
                    LDMATRIX_X4(b[np][0], b[np][1], b[np][2], b[np][3], addr);
                }
#pragma unroll
                for (int mi = 0; mi < 2; mi++)
#pragma unroll
                    for (int ni = 0; ni < 8; ni++)
                        MMA16816(c[mi][ni], a[mi], b[ni >> 1][(ni & 1) * 2], b[ni >> 1][(ni & 1) * 2 + 1]);
            }

            // ---- per-tile epilogue ----
            if (kc == 3) {
                const int colbase = ((i + (j >> 2)) & 63) * 128;
#pragma unroll
                for (int s = 0; s < 4; s++) {
                    const int mi = s >> 1, hf = s & 1;
                    float m = c[mi][0][hf * 2];
#pragma unroll
                    for (int ni = 0; ni < 8; ni++) {
                        m = fmaxf(m, c[mi][ni][hf * 2]);
                        m = fmaxf(m, c[mi][ni][hf * 2 + 1]);
                    }
                    m = fmaxf(m, __shfl_xor_sync(0xffffffffu, m, 1));
                    m = fmaxf(m, __shfl_xor_sync(0xffffffffu, m, 2));
                    bestv[s] = fmaxf(fmaxf(bestv[s], m), cached[s]);
                    const float thr = bestv[s] - MARGIN;
                    const int row = rows4[s];
#pragma unroll
                    for (int ni = 0; ni < 8; ni++) {
#pragma unroll
                        for (int r2 = 0; r2 < 2; r2++) {
                            float v = c[mi][ni][hf * 2 + r2];
                            if (v >= thr) {
                                int col = colbase + warp_n * 64 + ni * 8 + (lane & 3) * 2 + r2;
                                int slot = atomicAdd(&g_ccnt[row], 1);
                                if (slot < CAP) g_cand[row * CAP + slot] = col;
                            }
                        }
                    }
                    // publish + refresh (consumed next tile; latency hidden)
                    if ((lane & 3) == 0) atomicMax(&g_rowmax[row], fkey(bestv[s]));
                    cached[s] = funkey(__ldcg(&g_rowmax[row]));
                }
            }
            __syncthreads();
        }
#undef ISSUE_STAGE
        i = segend;
    }
}

// ---------------- exact fp32 refine + fused bincount + output write ---------
__device__ __forceinline__ float cand_dot(int cidx, const float4& f0, const float4& f1, int lane) {
    const float4* G = (const float4*)g_coden + (size_t)cidx * 64 + lane * 2;
    float4 g0 = G[0], g1 = G[1];
    return f0.x*g0.x + f0.y*g0.y + f0.z*g0.z + f0.w*g0.w
         + f1.x*g1.x + f1.y*g1.y + f1.z*g1.z + f1.w*g1.w;
}

__global__ void refine_kernel(float* __restrict__ out) {
    const int wid = threadIdx.x >> 5, lane = threadIdx.x & 31;
    const int row = blockIdx.x * 8 + wid;
    const float4* F = (const float4*)g_flatn + (size_t)row * 64 + lane * 2;
    const float4 f0 = F[0], f1 = F[1];
    int cnt = g_ccnt[row];
    float bv = -1e30f;
    int bi = 0x7fffffff;

    if (cnt <= CAP) {
        int j = 0;
        for (; j + 2 <= cnt; j += 2) {
            int c0 = g_cand[row * CAP + j];
            int c1 = g_cand[row * CAP + j + 1];
            float s0 = cand_dot(c0, f0, f1, lane);
            float s1 = cand_dot(c1, f0, f1, lane);
#pragma unroll
            for (int off = 16; off; off >>= 1) {
                s0 += __shfl_xor_sync(0xffffffffu, s0, off);
                s1 += __shfl_xor_sync(0xffffffffu, s1, off);
            }
            if (s0 > bv || (s0 == bv && c0 < bi)) { bv = s0; bi = c0; }
            if (s1 > bv || (s1 == bv && c1 < bi)) { bv = s1; bi = c1; }
        }
        if (j < cnt) {
            int c0 = g_cand[row * CAP + j];
            float s0 = cand_dot(c0, f0, f1, lane);
#pragma unroll
            for (int off = 16; off; off >>= 1) s0 += __shfl_xor_sync(0xffffffffu, s0, off);
            if (s0 > bv || (s0 == bv && c0 < bi)) { bv = s0; bi = c0; }
        }
    } else {
        // overflow fallback: exact scan over all codes
        for (int cidx = 0; cidx < EE; cidx++) {
            float s = cand_dot(cidx, f0, f1, lane);
#pragma unroll
            for (int off = 16; off; off >>= 1) s += __shfl_xor_sync(0xffffffffu, s, off);
            if (s > bv || (s == bv && cidx < bi)) { bv = s; bi = cidx; }
        }
    }
    if (lane == 0) {
        g_idx[row] = bi;
        g_sim[row] = bv;
        atomicAdd(&g_counts[bi], 1);   // fused bincount (integer: deterministic)
    }
    bi = __shfl_sync(0xffffffffu, bi, 0);

    // fused quantized output: out[row] = coden[bi] * g_scale
    float s = g_scale;
    const float4* Q = (const float4*)g_coden + (size_t)bi * 64 + lane * 2;
    float4 q0 = Q[0], q1 = Q[1];
    q0.x *= s; q0.y *= s; q0.z *= s; q0.w *= s;
    q1.x *= s; q1.y *= s; q1.z *= s; q1.w *= s;
    float4* O = (float4*)out + (size_t)row * 64 + lane * 2;
    O[0] = q0; O[1] = q1;
}

// ---------------- loss + perplexity ----------------
__global__ void finalize_kernel(float* __restrict__ out) {
    __shared__ float sh[1024];
    int tid = threadIdx.x;
    float s = 0.f;
    for (int i = tid; i < NN; i += 1024) s += g_sim[i];
    sh[tid] = s; __syncthreads();
    for (int off = 512; off; off >>= 1) {
        if (tid < off) sh[tid] += sh[tid + off];
        __syncthreads();
    }
    float sumS = sh[0];
    __syncthreads();
    float h = 0.f;
    for (int i = tid; i < EE; i += 1024) {
        float p = (float)g_counts[i] / (float)NN;
        h -= p * logf(p + 1e-10f);
    }
    sh[tid] = h; __syncthreads();
    for (int off = 512; off; off >>= 1) {
        if (tid < off) sh[tid] += sh[tid + off];
        __syncthreads();
    }
    if (tid == 0) {
        float loss = 1.25f * (2.0f * (float)NN - 2.0f * sumS) / (float)ND;
        out[ND]     = loss;
        out[ND + 1] = expf(sh[0]);
    }
}

// ---------------- launch ----------------
extern "C" void kernel_launch(void* const* d_in, const int* in_sizes, int n_in,
                              void* d_out, int out_size) {
    const float* inputs   = (const float*)d_in[0];
    const float* codebook = (const float*)d_in[1];
    float* out = (float*)d_out;

    cudaFuncSetAttribute(hh_gemm_kernel, cudaFuncAttributeMaxDynamicSharedMemorySize, SMEM_GEMM);

    normalize_inputs_kernel<<<NN / 8, 256>>>(inputs);
    normalize_codebook_kernel<<<EE / 8, 256>>>(codebook);
    hh_gemm_kernel<<<NG, 256, SMEM_GEMM>>>();
    refine_kernel<<<NN / 8, 256>>>(out);
    finalize_kernel<<<1, 1024>>>(out);
}

// round 8
// speedup vs baseline: 32.4583x; 1.0315x over previous
#include <cuda_runtime.h>
#include <cuda_fp16.h>
#include <math.h>
#include <stdint.h>

// Problem constants
#define NN 32768        // B*K rows
#define DD 256          // feature dim
#define EE 8192         // codebook entries
#define ND (NN*DD)
#define CAP 128         // candidate list capacity per row
#define MARGIN 0.0025f  // fp16 rounding slack (2 * 2^-10 = 0.00196 + headroom)
#define NTILES 16384    // 256 row-tiles x 64 code-tiles (128 codes each)
#define NG 296          // persistent grid (2 CTAs per SM on 148 SMs)

// ---------------- scratch (static __device__, no allocation) ----------------
__device__ __align__(16) __half g_Ah[NN * DD];
__device__ __align__(16) __half g_Bh[EE * DD];
__device__ __align__(16) float g_coden[EE * DD];   // fp32 normalized codebook
__device__ float g_invn[NN];                       // per-row 1/max(norm,eps)
__device__ float g_partial[NN / 8];
__device__ float g_scale;
__device__ int   g_idx[NN];
__device__ float g_sim[NN];
__device__ int   g_counts[EE];
__device__ int   g_ccnt[NN];
__device__ unsigned int g_rowmax[NN];              // monotone shared row max (keyed)
__device__ int   g_cand[NN * CAP];

// ---------------- PTX helpers ----------------
__device__ __forceinline__ uint32_t smem_u32(const void* p) {
    uint32_t a;
    asm("{ .reg .u64 t; cvta.to.shared.u64 t, %1; cvt.u32.u64 %0, t; }" : "=r"(a) : "l"(p));
    return a;
}
#define CP_ASYNC16(dst, src) \
    asm volatile("cp.async.cg.shared.global [%0], [%1], 16;" :: "r"(dst), "l"(src) : "memory")
#define CP_COMMIT() asm volatile("cp.async.commit_group;" ::: "memory")
#define CP_WAIT1()  asm volatile("cp.async.wait_group 1;" ::: "memory")
#define CP_WAIT0()  asm volatile("cp.async.wait_group 0;" ::: "memory")
#define LDMATRIX_X4(r0, r1, r2, r3, addr) \
    asm volatile("ldmatrix.sync.aligned.m8n8.x4.shared.b16 {%0,%1,%2,%3}, [%4];" \
        : "=r"(r0), "=r"(r1), "=r"(r2), "=r"(r3) : "r"(addr))
#define MMA16816(c, a, b0, b1) \
    asm volatile("mma.sync.aligned.m16n8k16.row.col.f32.f16.f16.f32 " \
        "{%0,%1,%2,%3}, {%4,%5,%6,%7}, {%8,%9}, {%0,%1,%2,%3};" \
        : "+f"((c)[0]), "+f"((c)[1]), "+f"((c)[2]), "+f"((c)[3]) \
        : "r"((a)[0]), "r"((a)[1]), "r"((a)[2]), "r"((a)[3]), "r"(b0), "r"(b1))

// order-preserving float<->uint key (for atomicMax on possibly-negative floats)
__device__ __forceinline__ uint32_t fkey(float f) {
    uint32_t u = __float_as_uint(f);
    return (u & 0x80000000u) ? ~u : (u | 0x80000000u);
}
__device__ __forceinline__ float funkey(uint32_t k) {
    uint32_t u = (k & 0x80000000u) ? (k & 0x7fffffffu) : ~k;
    return __uint_as_float(u);
}

// ---------------- fused prep: normalize inputs + codebook -------------------
// blocks [0, 4096): inputs (8 rows each) -> g_Ah fp16, g_invn, g_partial
// blocks [4096, 5120): codebook (8 rows each) -> g_coden fp32, g_Bh fp16
// zero-inits fused into the low blocks of each range.
__global__ void prep_kernel(const float* __restrict__ in, const float* __restrict__ cb) {
    const int warp = threadIdx.x >> 5, lane = threadIdx.x & 31;

    if (blockIdx.x < 4096) {
        if (blockIdx.x < 128) {
            int z = blockIdx.x * 256 + threadIdx.x;
            g_ccnt[z] = 0;
            g_rowmax[z] = 0u;        // key(-inf)
        }
        __shared__ float sh[8];
        int row = blockIdx.x * 8 + warp;
        const float4* r = (const float4*)in + (size_t)row * 64;
        float4 v0 = r[lane], v1 = r[lane + 32];
        float s = v0.x*v0.x + v0.y*v0.y + v0.z*v0.z + v0.w*v0.w
                + v1.x*v1.x + v1.y*v1.y + v1.z*v1.z + v1.w*v1.w;
#pragma unroll
        for (int off = 16; off; off >>= 1) s += __shfl_down_sync(0xffffffffu, s, off);
        s = __shfl_sync(0xffffffffu, s, 0);
        float nrm = sqrtf(s);
        float inv = 1.0f / fmaxf(nrm, 1e-12f);
        float4 n0 = make_float4(v0.x*inv, v0.y*inv, v0.z*inv, v0.w*inv);
        float4 n1 = make_float4(v1.x*inv, v1.y*inv, v1.z*inv, v1.w*inv);
        __half2 h0a = __floats2half2_rn(n0.x, n0.y);
        __half2 h0b = __floats2half2_rn(n0.z, n0.w);
        __half2 h1a = __floats2half2_rn(n1.x, n1.y);
        __half2 h1b = __floats2half2_rn(n1.z, n1.w);
        uint2 h0 = make_uint2(*(uint32_t*)&h0a, *(uint32_t*)&h0b);
        uint2 h1 = make_uint2(*(uint32_t*)&h1a, *(uint32_t*)&h1b);
        ((uint2*)g_Ah)[(size_t)row * 64 + lane]      = h0;
        ((uint2*)g_Ah)[(size_t)row * 64 + 32 + lane] = h1;
        if (lane == 0) {
            g_invn[row] = inv;
            sh[warp] = nrm;
        }
        __syncthreads();
        if (threadIdx.x == 0) {
            float t = 0.f;
#pragma unroll
            for (int w = 0; w < 8; w++) t += sh[w];
            g_partial[blockIdx.x] = t;
        }
    } else {
        int cbb = blockIdx.x - 4096;
        if (cbb < 32) g_counts[cbb * 256 + threadIdx.x] = 0;
        int row = cbb * 8 + warp;
        const float4* r = (const float4*)cb + (size_t)row * 64;
        float4 v0 = r[lane], v1 = r[lane + 32];
        float s = v0.x*v0.x + v0.y*v0.y + v0.z*v0.z + v0.w*v0.w
                + v1.x*v1.x + v1.y*v1.y + v1.z*v1.z + v1.w*v1.w;
#pragma unroll
        for (int off = 16; off; off >>= 1) s += __shfl_down_sync(0xffffffffu, s, off);
        s = __shfl_sync(0xffffffffu, s, 0);
        float inv = 1.0f / fmaxf(sqrtf(s), 1e-12f);
        float4 n0 = make_float4(v0.x*inv, v0.y*inv, v0.z*inv, v0.w*inv);
        float4 n1 = make_float4(v1.x*inv, v1.y*inv, v1.z*inv, v1.w*inv);
        ((float4*)g_coden)[(size_t)row * 64 + lane]      = n0;
        ((float4*)g_coden)[(size_t)row * 64 + 32 + lane] = n1;
        __half2 h0a = __floats2half2_rn(n0.x, n0.y);
        __half2 h0b = __floats2half2_rn(n0.z, n0.w);
        __half2 h1a = __floats2half2_rn(n1.x, n1.y);
        __half2 h1b = __floats2half2_rn(n1.z, n1.w);
        uint2 h0 = make_uint2(*(uint32_t*)&h0a, *(uint32_t*)&h0b);
        uint2 h1 = make_uint2(*(uint32_t*)&h1a, *(uint32_t*)&h1b);
        ((uint2*)g_Bh)[(size_t)row * 64 + lane]      = h0;
        ((uint2*)g_Bh)[(size_t)row * 64 + 32 + lane] = h1;
    }
}

// ---------------- balanced persistent fp16 GEMM + candidate capture ---------
// Work = 16384 tiles (128 rows x 128 codes x full K). CTA b owns a contiguous
// range (55-56 tiles, <=2 A reloads, 1.2% imbalance). Shared monotone per-row
// max keeps capture thresholds near-global. Block 0 additionally computes the
// mean-norm scale (hidden under the 400+ us GEMM).
#define SMEM_GEMM (65536 + 2 * 16384)

__device__ __forceinline__ uint32_t a_off(uint32_t r, uint32_t ch) {
    return r * 512u + (((ch & 0x18u) | ((ch ^ r) & 7u)) << 4);
}
__device__ __forceinline__ uint32_t b_off(uint32_t c, uint32_t ch) {
    return c * 128u + (((ch ^ c) & 7u) << 4);
}

__global__ void __launch_bounds__(256, 2) hh_gemm_kernel() {
    extern __shared__ __align__(1024) char smem[];
    const uint32_t sb = smem_u32(smem);
    const int tid = threadIdx.x;
    const int wid = tid >> 5;
    const int lane = tid & 31;
    const int warp_m = wid & 3;
    const int warp_n = wid >> 2;
    const uint4* Ag = (const uint4*)g_Ah;
    const uint4* Bg = (const uint4*)g_Bh;

    // fused deterministic mean-scale reduction (g_partial complete: prep done)
    if (blockIdx.x == 0) {
        __shared__ float shp[256];
        float s = 0.f;
        for (int i = tid; i < NN / 8; i += 256) s += g_partial[i];
        shp[tid] = s; __syncthreads();
        for (int off = 128; off; off >>= 1) {
            if (tid < off) shp[tid] += shp[tid + off];
            __syncthreads();
        }
        if (tid == 0) g_scale = shp[0] / (float)NN;
    }

    const int u0 = (int)(((long long)blockIdx.x * NTILES) / NG);
    const int u1 = (int)(((long long)(blockIdx.x + 1) * NTILES) / NG);

    int i = u0;
    while (i < u1) {
        const int rt = i >> 6;
        const int row0 = rt * 128;
        const int segend = min(u1, (rt + 1) << 6);
        const int nj = (segend - i) * 4;

        // ---- A tile load (own cp group) ----
#pragma unroll
        for (int l = 0; l < 16; l++) {
            int id = tid + l * 256;          // 0..4095
            uint32_t r = id >> 5, ch = id & 31;
            CP_ASYNC16(sb + a_off(r, ch), Ag + (size_t)(row0 + r) * 32 + ch);
        }
        CP_COMMIT();

        // ---- per-segment row state ----
        float bestv[4], cached[4];
        int rows4[4];
#pragma unroll
        for (int s = 0; s < 4; s++) {
            rows4[s] = row0 + warp_m * 32 + (s >> 1) * 16 + (lane >> 2) + (s & 1) * 8;
            bestv[s] = -1e30f;
            cached[s] = funkey(__ldcg(&g_rowmax[rows4[s]]));
        }

        // issue stage j: tile = i + (j>>2), k-chunk kc = j&3, buffer j&1
#define ISSUE_STAGE(j) do { \
            int _tl = i + ((j) >> 2), _kc = (j) & 3; \
            int _cb = (_tl & 63) * 128; \
            uint32_t _bb = sb + 65536 + ((j) & 1) * 16384; \
            _Pragma("unroll") \
            for (int _l = 0; _l < 4; _l++) { \
                int _id = tid + _l * 256; \
                uint32_t _c = _id >> 3, _ch = _id & 7; \
                CP_ASYNC16(_bb + b_off(_c, _ch), Bg + (size_t)(_cb + _c) * 32 + _kc * 8 + _ch); \
            } \
        } while (0)

        ISSUE_STAGE(0);
        CP_COMMIT();

        float c[2][8][4];

        for (int j = 0; j < nj; j++) {
            const int kc = j & 3;
            if (j + 1 < nj) {
                ISSUE_STAGE(j + 1);
                CP_COMMIT();
                CP_WAIT1();
            } else {
                CP_WAIT0();
            }
            __syncthreads();

            if (kc == 0) {
#pragma unroll
                for (int mi = 0; mi < 2; mi++)
#pragma unroll
                    for (int ni = 0; ni < 8; ni++)
#pragma unroll
                        for (int r2 = 0; r2 < 4; r2++) c[mi][ni][r2] = 0.f;
            }

            const uint32_t bb = sb + 65536 + (j & 1) * 16384;
#pragma unroll
            for (int ks = 0; ks < 4; ks++) {
                uint32_t a[2][4];
#pragma unroll
                for (int mi = 0; mi < 2; mi++) {
                    uint32_t r = warp_m * 32 + mi * 16 + (lane & 15);
                    uint32_t ch = kc * 8 + ks * 2 + (lane >> 4);
                    uint32_t addr = sb + a_off(r, ch);
                    LDMATRIX_X4(a[mi][0], a[mi][1], a[mi][2], a[mi][3], addr);
                }
                uint32_t b[4][4];
#pragma unroll
                for (int np = 0; np < 4; np++) {
                    uint32_t code = warp_n * 64 + np * 16 + (lane & 7) + ((lane & 16) ? 8 : 0);
                    uint32_t ch = ks * 2 + ((lane >> 3) & 1);
                    uint32_t addr = bb + b_off(code, ch);
                    LDMATRIX_X4(b[np][0], b[np][1], b[np][2], b[np][3], addr);
                }
#pragma unroll
                for (int mi = 0; mi < 2; mi++)
#pragma unroll
                    for (int ni = 0; ni < 8; ni++)
                        MMA16816(c[mi][ni], a[mi], b[ni >> 1][(ni & 1) * 2], b[ni >> 1][(ni & 1) * 2 + 1]);
            }

            // ---- per-tile epilogue ----
            if (kc == 3) {
                const int colbase = ((i + (j >> 2)) & 63) * 128;
#pragma unroll
                for (int s = 0; s < 4; s++) {
                    const int mi = s >> 1, hf = s & 1;
                    float m = c[mi][0][hf * 2];
#pragma unroll
                    for (int ni = 0; ni < 8; ni++) {
                        m = fmaxf(m, c[mi][ni][hf * 2]);
                        m = fmaxf(m, c[mi][ni][hf * 2 + 1]);
                    }
                    m = fmaxf(m, __shfl_xor_sync(0xffffffffu, m, 1));
                    m = fmaxf(m, __shfl_xor_sync(0xffffffffu, m, 2));
                    bestv[s] = fmaxf(fmaxf(bestv[s], m), cached[s]);
                    const float thr = bestv[s] - MARGIN;
                    const int row = rows4[s];
#pragma unroll
                    for (int ni = 0; ni < 8; ni++) {
#pragma unroll
                        for (int r2 = 0; r2 < 2; r2++) {
                            float v = c[mi][ni][hf * 2 + r2];
                            if (v >= thr) {
                                int col = colbase + warp_n * 64 + ni * 8 + (lane & 3) * 2 + r2;
                                int slot = atomicAdd(&g_ccnt[row], 1);
                                if (slot < CAP) g_cand[row * CAP + slot] = col;
                            }
                        }
                    }
                    // publish + refresh (consumed next tile; latency hidden)
                    if ((lane & 3) == 0) atomicMax(&g_rowmax[row], fkey(bestv[s]));
                    cached[s] = funkey(__ldcg(&g_rowmax[row]));
                }
            }
            __syncthreads();
        }
#undef ISSUE_STAGE
        i = segend;
    }
}

// ---------------- exact fp32 refine + fused bincount + output write ---------
__device__ __forceinline__ float cand_dot(int cidx, const float4& f0, const float4& f1, int lane) {
    const float4* G = (const float4*)g_coden + (size_t)cidx * 64 + lane * 2;
    float4 g0 = G[0], g1 = G[1];
    return f0.x*g0.x + f0.y*g0.y + f0.z*g0.z + f0.w*g0.w
         + f1.x*g1.x + f1.y*g1.y + f1.z*g1.z + f1.w*g1.w;
}

__global__ void refine_kernel(float* __restrict__ out, const float* __restrict__ in) {
    const int wid = threadIdx.x >> 5, lane = threadIdx.x & 31;
    const int row = blockIdx.x * 8 + wid;
    const float inv = g_invn[row];
    const float4* F = (const float4*)in + (size_t)row * 64 + lane * 2;
    float4 f0 = F[0], f1 = F[1];
    f0.x *= inv; f0.y *= inv; f0.z *= inv; f0.w *= inv;
    f1.x *= inv; f1.y *= inv; f1.z *= inv; f1.w *= inv;
    int cnt = g_ccnt[row];
    float bv = -1e30f;
    int bi = 0x7fffffff;

    if (cnt <= CAP) {
        int j = 0;
        for (; j + 2 <= cnt; j += 2) {
            int c0 = g_cand[row * CAP + j];
            int c1 = g_cand[row * CAP + j + 1];
            float s0 = cand_dot(c0, f0, f1, lane);
            float s1 = cand_dot(c1, f0, f1, lane);
#pragma unroll
            for (int off = 16; off; off >>= 1) {
                s0 += __shfl_xor_sync(0xffffffffu, s0, off);
                s1 += __shfl_xor_sync(0xffffffffu, s1, off);
            }
            if (s0 > bv || (s0 == bv && c0 < bi)) { bv = s0; bi = c0; }
            if (s1 > bv || (s1 == bv && c1 < bi)) { bv = s1; bi = c1; }
        }
        if (j < cnt) {
            int c0 = g_cand[row * CAP + j];
            float s0 = cand_dot(c0, f0, f1, lane);
#pragma unroll
            for (int off = 16; off; off >>= 1) s0 += __shfl_xor_sync(0xffffffffu, s0, off);
            if (s0 > bv || (s0 == bv && c0 < bi)) { bv = s0; bi = c0; }
        }
    } else {
        // overflow fallback: exact scan over all codes
        for (int cidx = 0; cidx < EE; cidx++) {
            float s = cand_dot(cidx, f0, f1, lane);
#pragma unroll
            for (int off = 16; off; off >>= 1) s += __shfl_xor_sync(0xffffffffu, s, off);
            if (s > bv || (s == bv && cidx < bi)) { bv = s; bi = cidx; }
        }
    }
    if (lane == 0) {
        g_idx[row] = bi;
        g_sim[row] = bv;
        atomicAdd(&g_counts[bi], 1);   // fused bincount (integer: deterministic)
    }
    bi = __shfl_sync(0xffffffffu, bi, 0);

    // fused quantized output: out[row] = coden[bi] * g_scale
    float s = g_scale;
    const float4* Q = (const float4*)g_coden + (size_t)bi * 64 + lane * 2;
    float4 q0 = Q[0], q1 = Q[1];
    q0.x *= s; q0.y *= s; q0.z *= s; q0.w *= s;
    q1.x *= s; q1.y *= s; q1.z *= s; q1.w *= s;
    float4* O = (float4*)out + (size_t)row * 64 + lane * 2;
    O[0] = q0; O[1] = q1;
}

// ---------------- loss + perplexity ----------------
__global__ void finalize_kernel(float* __restrict__ out) {
    __shared__ float sh[1024];
    int tid = threadIdx.x;
    float s = 0.f;
    const float4* S4 = (const float4*)g_sim;
    for (int i = tid; i < NN / 4; i += 1024) {
        float4 v = S4[i];
        s += (v.x + v.y) + (v.z + v.w);
    }
    sh[tid] = s; __syncthreads();
    for (int off = 512; off; off >>= 1) {
        if (tid < off) sh[tid] += sh[tid + off];
        __syncthreads();
    }
    float sumS = sh[0];
    __syncthreads();
    float h = 0.f;
    const int4* C4 = (const int4*)g_counts;
    for (int i = tid; i < EE / 4; i += 1024) {
        int4 c = C4[i];
        float p0 = (float)c.x / (float)NN, p1 = (float)c.y / (float)NN;
        float p2 = (float)c.z / (float)NN, p3 = (float)c.w / (float)NN;
        h -= p0 * logf(p0 + 1e-10f) + p1 * logf(p1 + 1e-10f)
           + p2 * logf(p2 + 1e-10f) + p3 * logf(p3 + 1e-10f);
    }
    sh[tid] = h; __syncthreads();
    for (int off = 512; off; off >>= 1) {
        if (tid < off) sh[tid] += sh[tid + off];
        __syncthreads();
    }
    if (tid == 0) {
        float loss = 1.25f * (2.0f * (float)NN - 2.0f * sumS) / (float)ND;
        out[ND]     = loss;
        out[ND + 1] = expf(sh[0]);
    }
}

// ---------------- launch ----------------
extern "C" void kernel_launch(void* const* d_in, const int* in_sizes, int n_in,
                              void* d_out, int out_size) {
    const float* inputs   = (const float*)d_in[0];
    const float* codebook = (const float*)d_in[1];
    float* out = (float*)d_out;

    cudaFuncSetAttribute(hh_gemm_kernel, cudaFuncAttributeMaxDynamicSharedMemorySize, SMEM_GEMM);

    prep_kernel<<<5120, 256>>>(inputs, codebook);
    hh_gemm_kernel<<<NG, 256, SMEM_GEMM>>>();
    refine_kernel<<<NN / 8, 256>>>(out, inputs);
    finalize_kernel<<<1, 1024>>>(out);
}